// round 2
// baseline (speedup 1.0000x reference)
#include <cuda_runtime.h>

// GRU decoder (Keras reset_after=True), B=32768, T=48, F=16, H=32, fp32.
// Two batch elements per thread packed into fp32x2 lanes; weights duplicated
// {w,w} in shared (uniform -> broadcast LDS); fma.rn.f32x2 does 2 MACs/inst.

typedef unsigned long long u64;

namespace {
constexpr int kB       = 32768;
constexpr int kT       = 48;
constexpr int kF       = 16;
constexpr int kH       = 32;
constexpr int kCTA     = 128;
constexpr int kThreads = kB / 2;          // 16384 threads, 2 batch each
constexpr int kGrid    = kThreads / kCTA; // 128 CTAs
}

__device__ __forceinline__ u64 pack2(float lo, float hi) {
    u64 r; asm("mov.b64 %0, {%1, %2};" : "=l"(r) : "f"(lo), "f"(hi)); return r;
}
__device__ __forceinline__ void unpack2(u64 v, float& lo, float& hi) {
    asm("mov.b64 {%0, %1}, %2;" : "=f"(lo), "=f"(hi) : "l"(v));
}
__device__ __forceinline__ u64 fma2(u64 a, u64 b, u64 c) {
    u64 d; asm("fma.rn.f32x2 %0, %1, %2, %3;" : "=l"(d) : "l"(a), "l"(b), "l"(c)); return d;
}
__device__ __forceinline__ float ex2a(float x) {
    float r; asm("ex2.approx.f32 %0, %1;" : "=f"(r) : "f"(x)); return r;
}
__device__ __forceinline__ float rcpa(float x) {
    float r; asm("rcp.approx.f32 %0, %1;" : "=f"(r) : "f"(x)); return r;
}
// sigmoid(x) = 1/(1 + 2^(-x*log2e)); saturates correctly at +/-inf
__device__ __forceinline__ float sig_fast(float x) {
    return rcpa(1.0f + ex2a(-1.4426950408889634f * x));
}
// tanh(x) = 1 - 2/(1 + 2^(2x*log2e)); saturates correctly at +/-inf
__device__ __forceinline__ float tanh_fast(float x) {
    return fmaf(-2.0f, rcpa(1.0f + ex2a(2.8853900817779268f * x)), 1.0f);
}
__device__ __forceinline__ void prefetchL2(const void* p) {
    asm volatile("prefetch.global.L2 [%0];" :: "l"(p));
}

#define SH64(x) (*reinterpret_cast<const u64*>(&(x)))

__global__ void __launch_bounds__(kCTA, 1)
gru_decoder_kernel(const float* __restrict__ feat,      // [B,T,F]
                   const float* __restrict__ init_in,   // [B,1]
                   const float* __restrict__ init_h,    // [B,H]
                   const float* __restrict__ kern,      // [1+F, 3H]
                   const float* __restrict__ rker,      // [H, 3H]
                   const float* __restrict__ bx,        // [3H]
                   const float* __restrict__ bh,        // [3H]
                   const float* __restrict__ dw,        // [H,1]
                   const float* __restrict__ db,        // [1]
                   float* __restrict__ out)             // [B,T,1]
{
    // Weights duplicated into both f32x2 lanes: element = {w, w}.
    // sR[g][j][k]: recurrent_kernel[k][g*32+j]   (k = 0..31)
    // sW[g][j][k]: kernel[k+1][g*32+j] for k<16; k==16 -> kernel[0][...] (prev_out)
    __shared__ __align__(16) float2 sR[3][kH][kH];   // 24 KB
    __shared__ __align__(16) float2 sW[3][kH][17];   // ~13 KB
    __shared__ __align__(16) float2 sBz[kH], sBr[kH], sBxh[kH], sBhh[kH];
    __shared__ float sDwS[kH];
    __shared__ float sDb;

    const int tid = threadIdx.x;
    for (int i = tid; i < 3 * kH * kH; i += kCTA) {
        int g = i / (kH * kH), rem = i % (kH * kH);
        int j = rem / kH, k = rem % kH;
        float w = rker[k * 96 + g * kH + j];
        sR[g][j][k] = make_float2(w, w);
    }
    for (int i = tid; i < 3 * kH * 17; i += kCTA) {
        int g = i / (kH * 17), rem = i % (kH * 17);
        int j = rem / 17, kk = rem % 17;
        int krow = (kk == 16) ? 0 : (kk + 1);
        float w = kern[krow * 96 + g * kH + j];
        sW[g][j][kk] = make_float2(w, w);
    }
    for (int j = tid; j < kH; j += kCTA) {
        float bz = bx[j] + bh[j];
        float br = bx[kH + j] + bh[kH + j];
        sBz[j]  = make_float2(bz, bz);
        sBr[j]  = make_float2(br, br);
        sBxh[j] = make_float2(bx[2 * kH + j], bx[2 * kH + j]);
        sBhh[j] = make_float2(bh[2 * kH + j], bh[2 * kH + j]);
        sDwS[j] = dw[j];
    }
    if (tid == 0) sDb = db[0];
    __syncthreads();

    const int gt = blockIdx.x * kCTA + tid;
    const int b0 = 2 * gt, b1 = b0 + 1;

    // h state: h[k] = {h_b0[k], h_b1[k]}  (32 aligned pairs)
    u64 h[kH];
    {
        const float4* h0p = reinterpret_cast<const float4*>(init_h + (size_t)b0 * kH);
        const float4* h1p = reinterpret_cast<const float4*>(init_h + (size_t)b1 * kH);
#pragma unroll
        for (int q = 0; q < kH / 4; q++) {
            float4 a = h0p[q], c = h1p[q];
            h[4 * q + 0] = pack2(a.x, c.x);
            h[4 * q + 1] = pack2(a.y, c.y);
            h[4 * q + 2] = pack2(a.z, c.z);
            h[4 * q + 3] = pack2(a.w, c.w);
        }
    }
    u64 prev2 = pack2(init_in[b0], init_in[b1]);

    const float4* f0p = reinterpret_cast<const float4*>(feat + (size_t)b0 * kT * kF);
    const float4* f1p = reinterpret_cast<const float4*>(feat + (size_t)b1 * kT * kF);
    float* o0p = out + (size_t)b0 * kT;
    float* o1p = out + (size_t)b1 * kT;
    const float dbv = sDb;

    prefetchL2(f0p);
    prefetchL2(f1p);

#pragma unroll 1
    for (int t = 0; t < kT; t++) {
        // Prefetch next step's features to L2 (each byte read exactly once -> cold).
        if (t + 1 < kT) {
            prefetchL2(f0p + (t + 1) * 4);
            prefetchL2(f1p + (t + 1) * 4);
        }
        // This step's features: 16 packed pairs {f_b0[k], f_b1[k]}
        float4 a0 = f0p[t * 4 + 0], a1 = f0p[t * 4 + 1],
               a2 = f0p[t * 4 + 2], a3 = f0p[t * 4 + 3];
        float4 c0 = f1p[t * 4 + 0], c1 = f1p[t * 4 + 1],
               c2 = f1p[t * 4 + 2], c3 = f1p[t * 4 + 3];
        u64 f2[kF];
        f2[ 0] = pack2(a0.x, c0.x); f2[ 1] = pack2(a0.y, c0.y);
        f2[ 2] = pack2(a0.z, c0.z); f2[ 3] = pack2(a0.w, c0.w);
        f2[ 4] = pack2(a1.x, c1.x); f2[ 5] = pack2(a1.y, c1.y);
        f2[ 6] = pack2(a1.z, c1.z); f2[ 7] = pack2(a1.w, c1.w);
        f2[ 8] = pack2(a2.x, c2.x); f2[ 9] = pack2(a2.y, c2.y);
        f2[10] = pack2(a2.z, c2.z); f2[11] = pack2(a2.w, c2.w);
        f2[12] = pack2(a3.x, c3.x); f2[13] = pack2(a3.y, c3.y);
        f2[14] = pack2(a3.z, c3.z); f2[15] = pack2(a3.w, c3.w);

        // next-state kept as scalar floats (no register-pair pressure)
        float hn0[kH], hn1[kH];
        float o0 = dbv, o1 = dbv;

#pragma unroll
        for (int j = 0; j < kH; j++) {
            u64 az = SH64(sBz[j]);
            u64 ar = SH64(sBr[j]);
            u64 ax = SH64(sBxh[j]);
            u64 ah = SH64(sBhh[j]);
#pragma unroll
            for (int k = 0; k < kH; k++) {
                az = fma2(h[k], SH64(sR[0][j][k]), az);
                ar = fma2(h[k], SH64(sR[1][j][k]), ar);
                ah = fma2(h[k], SH64(sR[2][j][k]), ah);
            }
#pragma unroll
            for (int k = 0; k < kF; k++) {
                az = fma2(f2[k], SH64(sW[0][j][k]), az);
                ar = fma2(f2[k], SH64(sW[1][j][k]), ar);
                ax = fma2(f2[k], SH64(sW[2][j][k]), ax);
            }
            az = fma2(prev2, SH64(sW[0][j][16]), az);
            ar = fma2(prev2, SH64(sW[1][j][16]), ar);
            ax = fma2(prev2, SH64(sW[2][j][16]), ax);

            float az0, az1, ar0, ar1, ax0, ax1, ah0, ah1;
            unpack2(az, az0, az1);
            unpack2(ar, ar0, ar1);
            unpack2(ax, ax0, ax1);
            unpack2(ah, ah0, ah1);
            float z0 = sig_fast(az0), z1 = sig_fast(az1);
            float r0 = sig_fast(ar0), r1 = sig_fast(ar1);
            float hh0 = tanh_fast(fmaf(r0, ah0, ax0));
            float hh1 = tanh_fast(fmaf(r1, ah1, ax1));
            float ho0, ho1;
            unpack2(h[j], ho0, ho1);
            float n0 = fmaf(z0, ho0 - hh0, hh0);   // z*h + (1-z)*hh
            float n1 = fmaf(z1, ho1 - hh1, hh1);
            hn0[j] = n0;
            hn1[j] = n1;
            float w = sDwS[j];
            o0 = fmaf(n0, w, o0);
            o1 = fmaf(n1, w, o1);
        }

        // commit state
#pragma unroll
        for (int k = 0; k < kH; k++) h[k] = pack2(hn0[k], hn1[k]);

        o0p[t] = o0;
        o1p[t] = o1;
        prev2 = pack2(o0, o1);
    }
}

extern "C" void kernel_launch(void* const* d_in, const int* in_sizes, int n_in,
                              void* d_out, int out_size) {
    (void)in_sizes; (void)n_in; (void)out_size;
    gru_decoder_kernel<<<kGrid, kCTA>>>(
        (const float*)d_in[0],   // decoder_feature
        (const float*)d_in[1],   // decoder_init_input
        (const float*)d_in[2],   // init_state
        (const float*)d_in[3],   // kernel
        (const float*)d_in[4],   // recurrent_kernel
        (const float*)d_in[5],   // bias_x
        (const float*)d_in[6],   // bias_h
        (const float*)d_in[7],   // dense_w
        (const float*)d_in[8],   // dense_b
        (float*)d_out);
}

// round 3
// speedup vs baseline: 1.7140x; 1.7140x over previous
#include <cuda_runtime.h>

// GRU decoder (Keras reset_after=True), B=32768, T=48, F=16, H=32, fp32.
// f32x2 lanes = 2 batch elements. 4 threads cooperate per batch-pair, each
// owning 8 of 32 output neurons; h replicated in regs, new-h exchanged via
// shfl(width=4). Weights duplicated {w,w} in shared, sub-interleaved so the
// 4 lanes of a group do conflict-free LDS.128.

typedef unsigned long long u64;
struct __align__(16) u64x2 { u64 x, y; };

namespace {
constexpr int kB    = 32768;
constexpr int kT    = 48;
constexpr int kF    = 16;
constexpr int kH    = 32;
constexpr int kCTA  = 128;
constexpr int kThreads = (kB / 2) * 4;      // 65536: 4 threads per batch-pair
constexpr int kGrid = kThreads / kCTA;      // 512 CTAs
}

__device__ __forceinline__ u64 pack2(float lo, float hi) {
    u64 r; asm("mov.b64 %0, {%1, %2};" : "=l"(r) : "f"(lo), "f"(hi)); return r;
}
__device__ __forceinline__ void unpack2(u64 v, float& lo, float& hi) {
    asm("mov.b64 {%0, %1}, %2;" : "=f"(lo), "=f"(hi) : "l"(v));
}
__device__ __forceinline__ u64 fma2(u64 a, u64 b, u64 c) {
    u64 d; asm("fma.rn.f32x2 %0, %1, %2, %3;" : "=l"(d) : "l"(a), "l"(b), "l"(c)); return d;
}
__device__ __forceinline__ float ex2a(float x) {
    float r; asm("ex2.approx.f32 %0, %1;" : "=f"(r) : "f"(x)); return r;
}
__device__ __forceinline__ float rcpa(float x) {
    float r; asm("rcp.approx.f32 %0, %1;" : "=f"(r) : "f"(x)); return r;
}
__device__ __forceinline__ float sig_fast(float x) {      // exact saturation at +/-inf
    return rcpa(1.0f + ex2a(-1.4426950408889634f * x));
}
__device__ __forceinline__ float tanh_fast(float x) {
    return fmaf(-2.0f, rcpa(1.0f + ex2a(2.8853900817779268f * x)), 1.0f);
}

__global__ void __launch_bounds__(kCTA)
gru_decoder_kernel(const float* __restrict__ feat,      // [B,T,F]
                   const float* __restrict__ init_in,   // [B,1]
                   const float* __restrict__ init_h,    // [B,H]
                   const float* __restrict__ kern,      // [1+F, 3H]
                   const float* __restrict__ rker,      // [H, 3H]
                   const float* __restrict__ bx,        // [3H]
                   const float* __restrict__ bh,        // [3H]
                   const float* __restrict__ dw,        // [H,1]
                   const float* __restrict__ db,        // [1]
                   float* __restrict__ out)             // [B,T,1]
{
    // Sub-interleaved duplicated weights. j = sub*8 + jj (sub = lane%4).
    // sR[g][jj][k2][sub][e]  = {w,w} for rker[2*k2+e][g*32+j]
    // sWx[g][jj][k2][sub][e] = {w,w} for kern[(2*k2+e)+1][g*32+j]   (features)
    // sWp[g][jj][sub]        = {w,w} for kern[0][g*32+j]            (prev_out)
    __shared__ __align__(16) u64 sR [3][8][16][4][2];   // 24 KB
    __shared__ __align__(16) u64 sWx[3][8][ 8][4][2];   // 12 KB
    __shared__ __align__(16) u64 sWp[3][8][4];
    __shared__ __align__(16) u64 sBz[8][4], sBr[8][4], sBxh[8][4], sBhh[8][4];
    __shared__ __align__(16) u64 sDw[8][4];
    __shared__ float sDb;

    const int tid = threadIdx.x;
    for (int i = tid; i < 3 * kH * kH; i += kCTA) {
        int g = i / (kH * kH), rem = i % (kH * kH);
        int j = rem / kH, k = rem % kH;
        float w = rker[k * 96 + g * kH + j];
        sR[g][j & 7][k >> 1][j >> 3][k & 1] = pack2(w, w);
    }
    for (int i = tid; i < 3 * kH * kF; i += kCTA) {
        int g = i / (kH * kF), rem = i % (kH * kF);
        int j = rem / kF, k = rem % kF;
        float w = kern[(k + 1) * 96 + g * kH + j];
        sWx[g][j & 7][k >> 1][j >> 3][k & 1] = pack2(w, w);
    }
    for (int i = tid; i < 3 * kH; i += kCTA) {
        int g = i / kH, j = i % kH;
        float w = kern[g * kH + j];
        sWp[g][j & 7][j >> 3] = pack2(w, w);
    }
    for (int j = tid; j < kH; j += kCTA) {
        float bz = bx[j] + bh[j];
        float br = bx[kH + j] + bh[kH + j];
        sBz [j & 7][j >> 3] = pack2(bz, bz);
        sBr [j & 7][j >> 3] = pack2(br, br);
        sBxh[j & 7][j >> 3] = pack2(bx[2 * kH + j], bx[2 * kH + j]);
        sBhh[j & 7][j >> 3] = pack2(bh[2 * kH + j], bh[2 * kH + j]);
        sDw [j & 7][j >> 3] = pack2(dw[j], dw[j]);
    }
    if (tid == 0) sDb = db[0];
    __syncthreads();

    const int gthread = blockIdx.x * kCTA + tid;
    const int pair = gthread >> 2;          // batch pair index
    const int sub  = tid & 3;               // which 8-neuron block I own
    const int b0 = 2 * pair, b1 = b0 + 1;

    // Full h replicated per thread: h[k] = {h_b0[k], h_b1[k]}
    u64 h[kH];
    {
        const float4* h0p = reinterpret_cast<const float4*>(init_h + (size_t)b0 * kH);
        const float4* h1p = reinterpret_cast<const float4*>(init_h + (size_t)b1 * kH);
#pragma unroll
        for (int q = 0; q < kH / 4; q++) {
            float4 a = h0p[q], c = h1p[q];
            h[4 * q + 0] = pack2(a.x, c.x);
            h[4 * q + 1] = pack2(a.y, c.y);
            h[4 * q + 2] = pack2(a.z, c.z);
            h[4 * q + 3] = pack2(a.w, c.w);
        }
    }
    u64 prev2 = pack2(init_in[b0], init_in[b1]);

    const float4* f0p = reinterpret_cast<const float4*>(feat + (size_t)b0 * kT * kF);
    const float4* f1p = reinterpret_cast<const float4*>(feat + (size_t)b1 * kT * kF);
    float* o0p = out + (size_t)b0 * kT;
    float* o1p = out + (size_t)b1 * kT;
    const float dbv = sDb;

#pragma unroll 1
    for (int t = 0; t < kT; t++) {
        float4 a0 = f0p[t * 4 + 0], a1 = f0p[t * 4 + 1],
               a2 = f0p[t * 4 + 2], a3 = f0p[t * 4 + 3];
        float4 c0 = f1p[t * 4 + 0], c1 = f1p[t * 4 + 1],
               c2 = f1p[t * 4 + 2], c3 = f1p[t * 4 + 3];
        u64 f2[kF];
        f2[ 0] = pack2(a0.x, c0.x); f2[ 1] = pack2(a0.y, c0.y);
        f2[ 2] = pack2(a0.z, c0.z); f2[ 3] = pack2(a0.w, c0.w);
        f2[ 4] = pack2(a1.x, c1.x); f2[ 5] = pack2(a1.y, c1.y);
        f2[ 6] = pack2(a1.z, c1.z); f2[ 7] = pack2(a1.w, c1.w);
        f2[ 8] = pack2(a2.x, c2.x); f2[ 9] = pack2(a2.y, c2.y);
        f2[10] = pack2(a2.z, c2.z); f2[11] = pack2(a2.w, c2.w);
        f2[12] = pack2(a3.x, c3.x); f2[13] = pack2(a3.y, c3.y);
        f2[14] = pack2(a3.z, c3.z); f2[15] = pack2(a3.w, c3.w);

        u64 hn[8];                 // my 8 new-state values (packed pairs)
        u64 oacc = pack2(0.0f, 0.0f);

#pragma unroll
        for (int jj = 0; jj < 8; jj++) {
            u64 az = sBz [jj][sub];
            u64 ar = sBr [jj][sub];
            u64 ax = sBxh[jj][sub];
            u64 ah = sBhh[jj][sub];
#pragma unroll
            for (int k2 = 0; k2 < kH / 2; k2++) {
                u64x2 wz = *reinterpret_cast<const u64x2*>(&sR[0][jj][k2][sub][0]);
                u64x2 wr = *reinterpret_cast<const u64x2*>(&sR[1][jj][k2][sub][0]);
                u64x2 wh = *reinterpret_cast<const u64x2*>(&sR[2][jj][k2][sub][0]);
                az = fma2(h[2 * k2],     wz.x, az);
                ar = fma2(h[2 * k2],     wr.x, ar);
                ah = fma2(h[2 * k2],     wh.x, ah);
                az = fma2(h[2 * k2 + 1], wz.y, az);
                ar = fma2(h[2 * k2 + 1], wr.y, ar);
                ah = fma2(h[2 * k2 + 1], wh.y, ah);
            }
#pragma unroll
            for (int k2 = 0; k2 < kF / 2; k2++) {
                u64x2 wz = *reinterpret_cast<const u64x2*>(&sWx[0][jj][k2][sub][0]);
                u64x2 wr = *reinterpret_cast<const u64x2*>(&sWx[1][jj][k2][sub][0]);
                u64x2 wx = *reinterpret_cast<const u64x2*>(&sWx[2][jj][k2][sub][0]);
                az = fma2(f2[2 * k2],     wz.x, az);
                ar = fma2(f2[2 * k2],     wr.x, ar);
                ax = fma2(f2[2 * k2],     wx.x, ax);
                az = fma2(f2[2 * k2 + 1], wz.y, az);
                ar = fma2(f2[2 * k2 + 1], wr.y, ar);
                ax = fma2(f2[2 * k2 + 1], wx.y, ax);
            }
            az = fma2(prev2, sWp[0][jj][sub], az);
            ar = fma2(prev2, sWp[1][jj][sub], ar);
            ax = fma2(prev2, sWp[2][jj][sub], ax);

            float az0, az1, ar0, ar1, ax0, ax1, ah0, ah1;
            unpack2(az, az0, az1);
            unpack2(ar, ar0, ar1);
            unpack2(ax, ax0, ax1);
            unpack2(ah, ah0, ah1);
            float z0 = sig_fast(az0), z1 = sig_fast(az1);
            float r0 = sig_fast(ar0), r1 = sig_fast(ar1);
            float hh0 = tanh_fast(fmaf(r0, ah0, ax0));
            float hh1 = tanh_fast(fmaf(r1, ah1, ax1));
            // my j = sub*8 + jj -> old h value lives at h[sub*8+jj]... but sub
            // is runtime; old h needed only for z*h term. h index = sub*8+jj:
            // avoid dynamic indexing by shuffling? No: h[] is replicated and
            // identical across lanes, so read via a small select below.
            float ho0, ho1;
            {
                // h[sub*8+jj]: sub in 0..3, jj unrolled. Select without
                // dynamic array indexing (4-way select on uniform sub).
                u64 hv = (sub == 0) ? h[jj] : (sub == 1) ? h[8 + jj]
                        : (sub == 2) ? h[16 + jj] : h[24 + jj];
                unpack2(hv, ho0, ho1);
            }
            float n0 = fmaf(z0, ho0 - hh0, hh0);
            float n1 = fmaf(z1, ho1 - hh1, hh1);
            hn[jj] = pack2(n0, n1);
            oacc = fma2(hn[jj], sDw[jj][sub], oacc);
        }

        // Exchange new h across the 4 lanes of the group (width-4 shuffles).
#pragma unroll
        for (int q = 0; q < 4; q++) {
#pragma unroll
            for (int jj = 0; jj < 8; jj++) {
                h[q * 8 + jj] = __shfl_sync(0xffffffffu, hn[jj], q, 4);
            }
        }

        // Dense output: reduce oacc over the 4 lanes (butterfly within group).
#pragma unroll
        for (int m = 1; m < 4; m <<= 1) {
            u64 o2 = __shfl_xor_sync(0xffffffffu, oacc, m, 4);
            float s0, s1, p0, p1;
            unpack2(oacc, s0, s1);
            unpack2(o2, p0, p1);
            oacc = pack2(s0 + p0, s1 + p1);
        }
        float s0, s1;
        unpack2(oacc, s0, s1);
        float out0 = s0 + dbv, out1 = s1 + dbv;
        if (sub == 0) {
            o0p[t] = out0;
            o1p[t] = out1;
        }
        prev2 = pack2(out0, out1);
    }
}

extern "C" void kernel_launch(void* const* d_in, const int* in_sizes, int n_in,
                              void* d_out, int out_size) {
    (void)in_sizes; (void)n_in; (void)out_size;
    gru_decoder_kernel<<<kGrid, kCTA>>>(
        (const float*)d_in[0],   // decoder_feature
        (const float*)d_in[1],   // decoder_init_input
        (const float*)d_in[2],   // init_state
        (const float*)d_in[3],   // kernel
        (const float*)d_in[4],   // recurrent_kernel
        (const float*)d_in[5],   // bias_x
        (const float*)d_in[6],   // bias_h
        (const float*)d_in[7],   // dense_w
        (const float*)d_in[8],   // dense_b
        (float*)d_out);
}

// round 4
// speedup vs baseline: 3.4931x; 2.0379x over previous
#include <cuda_runtime.h>

// GRU decoder (Keras reset_after=True), B=32768, T=48, F=16, H=32, fp32.
// Weight-stationary persistent-RNN style:
//   lane j of each warp owns neuron j; recurrent weights live in registers
//   (scalar, loaded once per warp). f32x2 lanes = 2 batch elements; each warp
//   processes 2 batch-pairs (4 batches) per group, h exchanged via warp
//   shuffles (no shared traffic). Input-part weights pre-duplicated {w,w} in
//   shared, read once per k per 4 batches.

typedef unsigned long long u64;

namespace {
constexpr int kT      = 48;
constexpr int kF      = 16;
constexpr int kH      = 32;
constexpr int kGroups = 8192;          // 32768 batches / 4 per group
constexpr int kCTA    = 128;           // 4 warps
constexpr int kGrid   = 296;           // 1184 warps, ~7 groups each
}

__device__ __forceinline__ u64 pack2(float lo, float hi) {
    u64 r; asm("mov.b64 %0, {%1, %2};" : "=l"(r) : "f"(lo), "f"(hi)); return r;
}
__device__ __forceinline__ void unpack2(u64 v, float& lo, float& hi) {
    asm("mov.b64 {%0, %1}, %2;" : "=f"(lo), "=f"(hi) : "l"(v));
}
__device__ __forceinline__ u64 fma2(u64 a, u64 b, u64 c) {
    u64 d; asm("fma.rn.f32x2 %0, %1, %2, %3;" : "=l"(d) : "l"(a), "l"(b), "l"(c)); return d;
}
__device__ __forceinline__ u64 add2(u64 a, u64 b) {
    u64 d; asm("add.rn.f32x2 %0, %1, %2;" : "=l"(d) : "l"(a), "l"(b)); return d;
}
__device__ __forceinline__ u64 shfl64(u64 v, int src) {
    float lo, hi; unpack2(v, lo, hi);
    lo = __shfl_sync(0xffffffffu, lo, src);
    hi = __shfl_sync(0xffffffffu, hi, src);
    return pack2(lo, hi);
}
__device__ __forceinline__ u64 shflxor64(u64 v, int m) {
    float lo, hi; unpack2(v, lo, hi);
    lo = __shfl_xor_sync(0xffffffffu, lo, m);
    hi = __shfl_xor_sync(0xffffffffu, hi, m);
    return pack2(lo, hi);
}
__device__ __forceinline__ float ex2a(float x) {
    float r; asm("ex2.approx.f32 %0, %1;" : "=f"(r) : "f"(x)); return r;
}
__device__ __forceinline__ float rcpa(float x) {
    float r; asm("rcp.approx.f32 %0, %1;" : "=f"(r) : "f"(x)); return r;
}
__device__ __forceinline__ float sig_fast(float x) {   // exact saturation at +/-inf
    return rcpa(1.0f + ex2a(-1.4426950408889634f * x));
}
__device__ __forceinline__ float tanh_fast(float x) {
    return fmaf(-2.0f, rcpa(1.0f + ex2a(2.8853900817779268f * x)), 1.0f);
}
__device__ __forceinline__ void prefetchL2(const void* p) {
    asm volatile("prefetch.global.L2 [%0];" :: "l"(p));
}

__global__ void __launch_bounds__(kCTA)
gru_decoder_kernel(const float* __restrict__ feat,      // [B,T,F]
                   const float* __restrict__ init_in,   // [B,1]
                   const float* __restrict__ init_h,    // [B,H]
                   const float* __restrict__ kern,      // [1+F, 3H]
                   const float* __restrict__ rker,      // [H, 3H]
                   const float* __restrict__ bx,        // [3H]
                   const float* __restrict__ bh,        // [3H]
                   const float* __restrict__ dw,        // [H,1]
                   const float* __restrict__ db,        // [1]
                   float* __restrict__ out)             // [B,T,1]
{
    // Input-part weights pre-duplicated {w,w}: sWin[g][k][j], k=0 is prev_out
    // row (kern row 0), k=1..16 are feature rows. Per-k lane reads are 256B
    // contiguous -> conflict-free 2-wavefront LDS.64.
    __shared__ __align__(16) u64 sWin[3][17][kH];   // ~13 KB

    const int tid = threadIdx.x;
    for (int i = tid; i < 3 * 17 * kH; i += kCTA) {
        int g = i / (17 * kH), rem = i % (17 * kH);
        int k = rem / kH, j = rem % kH;
        float w = kern[k * 96 + g * kH + j];
        sWin[g][k][j] = pack2(w, w);
    }
    __syncthreads();

    const int lane = tid & 31;
    const int warp_global = (blockIdx.x * kCTA + tid) >> 5;
    const int nwarps = kGrid * (kCTA / 32);

    // Recurrent weights, scalar, register-resident (lane j = neuron j).
    float Rz[kH], Rr[kH], Rh[kH];
#pragma unroll
    for (int k = 0; k < kH; k++) {
        Rz[k] = rker[k * 96 + lane];
        Rr[k] = rker[k * 96 + kH + lane];
        Rh[k] = rker[k * 96 + 2 * kH + lane];
    }
    const float bzs = bx[lane] + bh[lane];
    const float brs = bx[kH + lane] + bh[kH + lane];
    const float bxh = bx[2 * kH + lane];
    const float bhh = bh[2 * kH + lane];
    const u64 dw2 = pack2(dw[lane], dw[lane]);
    const float dbv = db[0];

#pragma unroll 1
    for (int grp = warp_global; grp < kGroups; grp += nwarps) {
        const int bA0 = 4 * grp, bA1 = bA0 + 1, bB0 = bA0 + 2, bB1 = bA0 + 3;

        // h pairs: hA = {h_bA0[lane], h_bA1[lane]}
        u64 hA = pack2(init_h[(size_t)bA0 * kH + lane], init_h[(size_t)bA1 * kH + lane]);
        u64 hB = pack2(init_h[(size_t)bB0 * kH + lane], init_h[(size_t)bB1 * kH + lane]);
        u64 prevA = pack2(init_in[bA0], init_in[bA1]);
        u64 prevB = pack2(init_in[bB0], init_in[bB1]);

        const float4* fA0 = reinterpret_cast<const float4*>(feat + (size_t)bA0 * kT * kF);
        const float4* fA1 = reinterpret_cast<const float4*>(feat + (size_t)bA1 * kT * kF);
        const float4* fB0 = reinterpret_cast<const float4*>(feat + (size_t)bB0 * kT * kF);
        const float4* fB1 = reinterpret_cast<const float4*>(feat + (size_t)bB1 * kT * kF);
        float* oA0 = out + (size_t)bA0 * kT;

        prefetchL2(fA0); prefetchL2(fA1); prefetchL2(fB0); prefetchL2(fB1);

#pragma unroll 1
        for (int t = 0; t < kT; t++) {
            if (t + 1 < kT) {
                prefetchL2(fA0 + (t + 1) * 4); prefetchL2(fA1 + (t + 1) * 4);
                prefetchL2(fB0 + (t + 1) * 4); prefetchL2(fB1 + (t + 1) * 4);
            }
            // Feature loads (broadcast LDG; consumed after the recurrent part,
            // giving the loads latency cover).
            float4 a0 = fA0[t * 4 + 0], a1 = fA0[t * 4 + 1],
                   a2 = fA0[t * 4 + 2], a3 = fA0[t * 4 + 3];
            float4 b0 = fA1[t * 4 + 0], b1 = fA1[t * 4 + 1],
                   b2 = fA1[t * 4 + 2], b3 = fA1[t * 4 + 3];
            float4 c0 = fB0[t * 4 + 0], c1 = fB0[t * 4 + 1],
                   c2 = fB0[t * 4 + 2], c3 = fB0[t * 4 + 3];
            float4 d0 = fB1[t * 4 + 0], d1 = fB1[t * 4 + 1],
                   d2 = fB1[t * 4 + 2], d3 = fB1[t * 4 + 3];
            u64 fpA[kF], fpB[kF];
            fpA[ 0]=pack2(a0.x,b0.x); fpA[ 1]=pack2(a0.y,b0.y); fpA[ 2]=pack2(a0.z,b0.z); fpA[ 3]=pack2(a0.w,b0.w);
            fpA[ 4]=pack2(a1.x,b1.x); fpA[ 5]=pack2(a1.y,b1.y); fpA[ 6]=pack2(a1.z,b1.z); fpA[ 7]=pack2(a1.w,b1.w);
            fpA[ 8]=pack2(a2.x,b2.x); fpA[ 9]=pack2(a2.y,b2.y); fpA[10]=pack2(a2.z,b2.z); fpA[11]=pack2(a2.w,b2.w);
            fpA[12]=pack2(a3.x,b3.x); fpA[13]=pack2(a3.y,b3.y); fpA[14]=pack2(a3.z,b3.z); fpA[15]=pack2(a3.w,b3.w);
            fpB[ 0]=pack2(c0.x,d0.x); fpB[ 1]=pack2(c0.y,d0.y); fpB[ 2]=pack2(c0.z,d0.z); fpB[ 3]=pack2(c0.w,d0.w);
            fpB[ 4]=pack2(c1.x,d1.x); fpB[ 5]=pack2(c1.y,d1.y); fpB[ 6]=pack2(c1.z,d1.z); fpB[ 7]=pack2(c1.w,d1.w);
            fpB[ 8]=pack2(c2.x,d2.x); fpB[ 9]=pack2(c2.z,d2.y); fpB[10]=pack2(c2.z,d2.z); fpB[11]=pack2(c2.w,d2.w);
            fpB[ 9]=pack2(c2.y,d2.y);
            fpB[12]=pack2(c3.x,d3.x); fpB[13]=pack2(c3.y,d3.y); fpB[14]=pack2(c3.z,d3.z); fpB[15]=pack2(c3.w,d3.w);

            // Accumulators (z and r combine both bias terms; hh keeps x-side
            // and h-side separate for the reset gate).
            u64 azA = pack2(bzs, bzs), azB = azA;
            u64 arA = pack2(brs, brs), arB = arA;
            u64 axA = pack2(bxh, bxh), axB = axA;
            u64 ahA = pack2(bhh, bhh), ahB = ahA;

            // Recurrent part: h broadcast by shuffle, weights dup'd from RF.
#pragma unroll
            for (int k = 0; k < kH; k++) {
                u64 hkA = shfl64(hA, k);
                u64 hkB = shfl64(hB, k);
                u64 wz = pack2(Rz[k], Rz[k]);
                u64 wr = pack2(Rr[k], Rr[k]);
                u64 wh = pack2(Rh[k], Rh[k]);
                azA = fma2(hkA, wz, azA); azB = fma2(hkB, wz, azB);
                arA = fma2(hkA, wr, arA); arB = fma2(hkB, wr, arB);
                ahA = fma2(hkA, wh, ahA); ahB = fma2(hkB, wh, ahB);
            }
            // Input part: weights from shared (pre-dup'd), shared across pairs.
#pragma unroll
            for (int k = 0; k < 17; k++) {
                u64 wz = sWin[0][k][lane];
                u64 wr = sWin[1][k][lane];
                u64 wx = sWin[2][k][lane];
                u64 xA = (k == 0) ? prevA : fpA[k - 1];
                u64 xB = (k == 0) ? prevB : fpB[k - 1];
                azA = fma2(xA, wz, azA); azB = fma2(xB, wz, azB);
                arA = fma2(xA, wr, arA); arB = fma2(xB, wr, arB);
                axA = fma2(xA, wx, axA); axB = fma2(xB, wx, axB);
            }

            // Activations + state update (per pair).
            float z0, z1, r0, r1, x0, x1, g0, g1, h0, h1;
            unpack2(azA, z0, z1); unpack2(arA, r0, r1);
            unpack2(axA, x0, x1); unpack2(ahA, g0, g1);
            z0 = sig_fast(z0); z1 = sig_fast(z1);
            r0 = sig_fast(r0); r1 = sig_fast(r1);
            float hh0 = tanh_fast(fmaf(r0, g0, x0));
            float hh1 = tanh_fast(fmaf(r1, g1, x1));
            unpack2(hA, h0, h1);
            hA = pack2(fmaf(z0, h0 - hh0, hh0), fmaf(z1, h1 - hh1, hh1));

            unpack2(azB, z0, z1); unpack2(arB, r0, r1);
            unpack2(axB, x0, x1); unpack2(ahB, g0, g1);
            z0 = sig_fast(z0); z1 = sig_fast(z1);
            r0 = sig_fast(r0); r1 = sig_fast(r1);
            hh0 = tanh_fast(fmaf(r0, g0, x0));
            hh1 = tanh_fast(fmaf(r1, g1, x1));
            unpack2(hB, h0, h1);
            hB = pack2(fmaf(z0, h0 - hh0, hh0), fmaf(z1, h1 - hh1, hh1));

            // Dense output: butterfly reduce (result lands in all lanes).
            u64 oA = fma2(hA, dw2, pack2(0.0f, 0.0f));
            u64 oB = fma2(hB, dw2, pack2(0.0f, 0.0f));
#pragma unroll
            for (int m = 16; m >= 1; m >>= 1) {
                oA = add2(oA, shflxor64(oA, m));
                oB = add2(oB, shflxor64(oB, m));
            }
            float oA0v, oA1v, oB0v, oB1v;
            unpack2(oA, oA0v, oA1v);
            unpack2(oB, oB0v, oB1v);
            oA0v += dbv; oA1v += dbv; oB0v += dbv; oB1v += dbv;
            prevA = pack2(oA0v, oA1v);
            prevB = pack2(oB0v, oB1v);
            if (lane == 0) {
                oA0[t]           = oA0v;   // batch bA0
                oA0[kT + t]      = oA1v;   // batch bA1
                oA0[2 * kT + t]  = oB0v;   // batch bB0
                oA0[3 * kT + t]  = oB1v;   // batch bB1
            }
        }
    }
}

extern "C" void kernel_launch(void* const* d_in, const int* in_sizes, int n_in,
                              void* d_out, int out_size) {
    (void)in_sizes; (void)n_in; (void)out_size;
    gru_decoder_kernel<<<kGrid, kCTA>>>(
        (const float*)d_in[0],   // decoder_feature
        (const float*)d_in[1],   // decoder_init_input
        (const float*)d_in[2],   // init_state
        (const float*)d_in[3],   // kernel
        (const float*)d_in[4],   // recurrent_kernel
        (const float*)d_in[5],   // bias_x
        (const float*)d_in[6],   // bias_h
        (const float*)d_in[7],   // dense_w
        (const float*)d_in[8],   // dense_b
        (float*)d_out);
}

// round 5
// speedup vs baseline: 4.2967x; 1.2301x over previous
#include <cuda_runtime.h>
#include <cstdint>

// GRU decoder (Keras reset_after=True), B=32768, T=48, F=16, H=32, fp32.
// Lane j owns neuron j; ALL weights register-resident scalars (147/lane).
// f32x2 lanes = 2 batch elements; each warp runs 2 pairs (4 batches).
// h and features broadcast via per-warp shared buffers (broadcast LDS.128,
// 1 wavefront) instead of shuffles. Double-buffered, one __syncwarp/step.

typedef unsigned long long u64;

namespace {
constexpr int kT     = 48;
constexpr int kF     = 16;
constexpr int kH     = 32;
constexpr int kTasks = 8192;             // 32768 batches / 4 per task
constexpr int kCTA   = 128;              // 4 warps
constexpr int kGrid  = 296;              // 2 CTAs/SM, 1184 warps
constexpr int kWarps = kGrid * (kCTA / 32);
}

__device__ __forceinline__ u64 pack2(float lo, float hi) {
    u64 r; asm("mov.b64 %0, {%1, %2};" : "=l"(r) : "f"(lo), "f"(hi)); return r;
}
__device__ __forceinline__ void unpack2(u64 v, float& lo, float& hi) {
    asm("mov.b64 {%0, %1}, %2;" : "=f"(lo), "=f"(hi) : "l"(v));
}
__device__ __forceinline__ u64 fma2(u64 a, u64 b, u64 c) {
    u64 d; asm("fma.rn.f32x2 %0, %1, %2, %3;" : "=l"(d) : "l"(a), "l"(b), "l"(c)); return d;
}
__device__ __forceinline__ float ex2a(float x) {
    float r; asm("ex2.approx.f32 %0, %1;" : "=f"(r) : "f"(x)); return r;
}
__device__ __forceinline__ float rcpa(float x) {
    float r; asm("rcp.approx.f32 %0, %1;" : "=f"(r) : "f"(x)); return r;
}
__device__ __forceinline__ float sig_fast(float x) {   // exact saturation at +/-inf
    return rcpa(1.0f + ex2a(-1.4426950408889634f * x));
}
__device__ __forceinline__ float tanh_fast(float x) {
    return fmaf(-2.0f, rcpa(1.0f + ex2a(2.8853900817779268f * x)), 1.0f);
}
__device__ __forceinline__ uint32_t smem_u32(const void* p) {
    return (uint32_t)__cvta_generic_to_shared(p);
}
__device__ __forceinline__ void sts128(uint32_t a, float x, float y, float z, float w) {
    asm volatile("st.shared.v4.f32 [%0], {%1,%2,%3,%4};"
                 :: "r"(a), "f"(x), "f"(y), "f"(z), "f"(w));
}
__device__ __forceinline__ void lds128(uint32_t a, u64& x, u64& y) {
    asm volatile("ld.shared.v2.u64 {%0,%1}, [%2];" : "=l"(x), "=l"(y) : "r"(a));
}
__device__ __forceinline__ void prefetchL2(const void* p) {
    asm volatile("prefetch.global.L2 [%0];" :: "l"(p));
}
__device__ __forceinline__ float redsum(float v) {   // xor butterfly, all lanes get sum
#pragma unroll
    for (int m = 16; m >= 1; m >>= 1) v += __shfl_xor_sync(0xffffffffu, v, m);
    return v;
}

__global__ void __launch_bounds__(kCTA)
gru_decoder_kernel(const float* __restrict__ feat,      // [B,T,F]
                   const float* __restrict__ init_in,   // [B,1]
                   const float* __restrict__ init_h,    // [B,H]
                   const float* __restrict__ kern,      // [1+F, 3H]
                   const float* __restrict__ rker,      // [H, 3H]
                   const float* __restrict__ bx,        // [3H]
                   const float* __restrict__ bh,        // [3H]
                   const float* __restrict__ dw,        // [H,1]
                   const float* __restrict__ db,        // [1]
                   float* __restrict__ out)             // [B,T,1]
{
    // Per-warp broadcast buffers, double-buffered.
    // shH[w][buf][j] = {hA0,hA1, hB0,hB1} of lane j (as 2 u64 pairs)
    // shX[w][buf][k] = {fA0,fA1, fB0,fB1} feature k (as 2 u64 pairs)
    __shared__ __align__(16) float shH[4][2][kH][4];
    __shared__ __align__(16) float shX[4][2][kF][4];

    const int tid  = threadIdx.x;
    const int wip  = tid >> 5;
    const int lane = tid & 31;

    // Register-resident weights for my neuron (lane).
    float Rz[kH], Rr[kH], Rh[kH];
#pragma unroll
    for (int k = 0; k < kH; k++) {
        Rz[k] = rker[k * 96 + lane];
        Rr[k] = rker[k * 96 + kH + lane];
        Rh[k] = rker[k * 96 + 2 * kH + lane];
    }
    float Wz[17], Wr[17], Wx[17];   // k=0: prev_out row; k>=1: feature rows
#pragma unroll
    for (int k = 0; k < 17; k++) {
        Wz[k] = kern[k * 96 + lane];
        Wr[k] = kern[k * 96 + kH + lane];
        Wx[k] = kern[k * 96 + 2 * kH + lane];
    }
    const float bzv = bx[lane] + bh[lane];
    const float brv = bx[kH + lane] + bh[kH + lane];
    const u64 bz2 = pack2(bzv, bzv);
    const u64 br2 = pack2(brv, brv);
    const u64 bx2 = pack2(bx[2 * kH + lane], bx[2 * kH + lane]);
    const u64 bh2 = pack2(bh[2 * kH + lane], bh[2 * kH + lane]);
    const float dwl = dw[lane];
    const float dbv = db[0];

    const uint32_t shHbase = smem_u32(&shH[wip][0][0][0]);
    const uint32_t shXbase = smem_u32(&shX[wip][0][0][0]);

    const int wg = (blockIdx.x * kCTA + tid) >> 5;

#pragma unroll 1
    for (int task = wg; task < kTasks; task += kWarps) {
        const int b0 = 4 * task, b1 = b0 + 1, b2 = b0 + 2, b3 = b0 + 3;

        float hA0 = init_h[(size_t)b0 * kH + lane];
        float hA1 = init_h[(size_t)b1 * kH + lane];
        float hB0 = init_h[(size_t)b2 * kH + lane];
        float hB1 = init_h[(size_t)b3 * kH + lane];
        float pA0 = init_in[b0], pA1 = init_in[b1];
        float pB0 = init_in[b2], pB1 = init_in[b3];

        const float* f0 = feat + (size_t)b0 * kT * kF;
        const float* f1 = feat + (size_t)b1 * kT * kF;
        const float* f2 = feat + (size_t)b2 * kT * kF;
        const float* f3 = feat + (size_t)b3 * kT * kF;
        float* ob = out + (size_t)b0 * kT;

        // Stage features for t=0 (lanes 0..15, coalesced 64B rows).
        float fv0 = 0.f, fv1 = 0.f, fv2 = 0.f, fv3 = 0.f;
        if (lane < kF) {
            fv0 = f0[lane]; fv1 = f1[lane]; fv2 = f2[lane]; fv3 = f3[lane];
            prefetchL2(f0 + kF); prefetchL2(f1 + kF);
            prefetchL2(f2 + kF); prefetchL2(f3 + kF);
        }

#pragma unroll 1
        for (int t = 0; t < kT; t++) {
            const uint32_t bufH = shHbase + (uint32_t)(t & 1) * (kH * 16);
            const uint32_t bufX = shXbase + (uint32_t)(t & 1) * (kF * 16);

            // Publish my state + staged features.
            sts128(bufH + lane * 16, hA0, hA1, hB0, hB1);
            if (lane < kF) sts128(bufX + lane * 16, fv0, fv1, fv2, fv3);
            __syncwarp();

            // Load next step's features now (latency covered by the mainloop).
            if (lane < kF) {
                int tn = (t + 1 < kT) ? t + 1 : t;
                fv0 = f0[tn * kF + lane]; fv1 = f1[tn * kF + lane];
                fv2 = f2[tn * kF + lane]; fv3 = f3[tn * kF + lane];
            }

            u64 azA = bz2, azB = bz2;
            u64 arA = br2, arB = br2;
            u64 axA = bx2, axB = bx2;
            u64 ahA = bh2, ahB = bh2;

            // Recurrent part: broadcast LDS (1 wavefront), weights dup'd from RF.
#pragma unroll
            for (int k = 0; k < kH; k++) {
                u64 hkA, hkB;
                lds128(bufH + k * 16, hkA, hkB);
                u64 wz = pack2(Rz[k], Rz[k]);
                u64 wr = pack2(Rr[k], Rr[k]);
                u64 wh = pack2(Rh[k], Rh[k]);
                azA = fma2(hkA, wz, azA); azB = fma2(hkB, wz, azB);
                arA = fma2(hkA, wr, arA); arB = fma2(hkB, wr, arB);
                ahA = fma2(hkA, wh, ahA); ahB = fma2(hkB, wh, ahB);
            }
            // prev_out term (uniform in registers, no broadcast needed).
            {
                u64 pA = pack2(pA0, pA1), pB = pack2(pB0, pB1);
                u64 wz = pack2(Wz[0], Wz[0]);
                u64 wr = pack2(Wr[0], Wr[0]);
                u64 wx = pack2(Wx[0], Wx[0]);
                azA = fma2(pA, wz, azA); azB = fma2(pB, wz, azB);
                arA = fma2(pA, wr, arA); arB = fma2(pB, wr, arB);
                axA = fma2(pA, wx, axA); axB = fma2(pB, wx, axB);
            }
            // Feature part: broadcast LDS.
#pragma unroll
            for (int k = 0; k < kF; k++) {
                u64 xkA, xkB;
                lds128(bufX + k * 16, xkA, xkB);
                u64 wz = pack2(Wz[k + 1], Wz[k + 1]);
                u64 wr = pack2(Wr[k + 1], Wr[k + 1]);
                u64 wx = pack2(Wx[k + 1], Wx[k + 1]);
                azA = fma2(xkA, wz, azA); azB = fma2(xkB, wz, azB);
                arA = fma2(xkA, wr, arA); arB = fma2(xkB, wr, arB);
                axA = fma2(xkA, wx, axA); axB = fma2(xkB, wx, axB);
            }

            // Activations + state update.
            float z0, z1, r0, r1, x0, x1, g0, g1;
            unpack2(azA, z0, z1); unpack2(arA, r0, r1);
            unpack2(axA, x0, x1); unpack2(ahA, g0, g1);
            z0 = sig_fast(z0); z1 = sig_fast(z1);
            r0 = sig_fast(r0); r1 = sig_fast(r1);
            float hh0 = tanh_fast(fmaf(r0, g0, x0));
            float hh1 = tanh_fast(fmaf(r1, g1, x1));
            hA0 = fmaf(z0, hA0 - hh0, hh0);
            hA1 = fmaf(z1, hA1 - hh1, hh1);

            unpack2(azB, z0, z1); unpack2(arB, r0, r1);
            unpack2(axB, x0, x1); unpack2(ahB, g0, g1);
            z0 = sig_fast(z0); z1 = sig_fast(z1);
            r0 = sig_fast(r0); r1 = sig_fast(r1);
            hh0 = tanh_fast(fmaf(r0, g0, x0));
            hh1 = tanh_fast(fmaf(r1, g1, x1));
            hB0 = fmaf(z0, hB0 - hh0, hh0);
            hB1 = fmaf(z1, hB1 - hh1, hh1);

            // Dense(1): butterfly-reduce; every lane ends with the sums.
            float oA0 = redsum(hA0 * dwl) + dbv;
            float oA1 = redsum(hA1 * dwl) + dbv;
            float oB0 = redsum(hB0 * dwl) + dbv;
            float oB1 = redsum(hB1 * dwl) + dbv;
            pA0 = oA0; pA1 = oA1; pB0 = oB0; pB1 = oB1;
            if (lane == 0) {
                ob[t]          = oA0;
                ob[kT + t]     = oA1;
                ob[2 * kT + t] = oB0;
                ob[3 * kT + t] = oB1;
            }
        }
    }
}

extern "C" void kernel_launch(void* const* d_in, const int* in_sizes, int n_in,
                              void* d_out, int out_size) {
    (void)in_sizes; (void)n_in; (void)out_size;
    gru_decoder_kernel<<<kGrid, kCTA>>>(
        (const float*)d_in[0],   // decoder_feature
        (const float*)d_in[1],   // decoder_init_input
        (const float*)d_in[2],   // init_state
        (const float*)d_in[3],   // kernel
        (const float*)d_in[4],   // recurrent_kernel
        (const float*)d_in[5],   // bias_x
        (const float*)d_in[6],   // bias_h
        (const float*)d_in[7],   // dense_w
        (const float*)d_in[8],   // dense_b
        (float*)d_out);
}